// round 8
// baseline (speedup 1.0000x reference)
#include <cuda_runtime.h>
#include <math.h>

#define N_ROWS 8000
#define D_DIM  9
#define CHUNK  1000            // rows per chunk in the fused prep kernel
#define NCHUNK 8               // 8 * 1000 = 8000
#define CH_FLT (CHUNK * D_DIM) // 9000 floats per chunk
#define CH_V4  (CH_FLT / 4)    // 2250 float4 per chunk (exact)

// Scratch: device globals (no allocation allowed anywhere)
__device__ float g_df[N_ROWS];    // f1 - f2
__device__ float g_f2[N_ROWS];
__device__ float g_wbar[N_ROWS];  // sigmoid(cumsum(s2 - s1))

// ---------------------------------------------------------------------------
// Fused prep: row stats + inclusive scan + sigmoid, single block, 1024 thr.
// 8 chunks of 1000 rows. Double-buffered smem staging with register prefetch
// so chunk c+1's DRAM loads fly while chunk c is computed/scanned.
// ---------------------------------------------------------------------------
__global__ void __launch_bounds__(1024) k_prep(
    const float* __restrict__ x,
    const float* __restrict__ a1p, const float* __restrict__ c1p,
    const float* __restrict__ a2p, const float* __restrict__ c2p,
    const float* __restrict__ w1,  const float* __restrict__ b1,
    const float* __restrict__ w2,  const float* __restrict__ b2)
{
    __shared__ float s_x[2][CH_FLT];   // 2 x 36 KB
    __shared__ float s_warp[32];

    const int tid  = threadIdx.x;
    const int lane = tid & 31;
    const int wid  = tid >> 5;

    const float a1 = a1p[0], c1 = c1p[0], a2 = a2p[0], c2 = c2p[0];
    const float inv_a1 = 1.0f / a1, inv_a2 = 1.0f / a2;
    const float b1v = b1[0], b2v = b2[0];

    // FC weights in registers (broadcast loads, cached)
    float w1r[D_DIM], w2r[D_DIM];
#pragma unroll
    for (int d = 0; d < D_DIM; d++) { w1r[d] = w1[d]; w2r[d] = w2[d]; }

    const float4* __restrict__ x4 = (const float4*)x;

    // Prefetch chunk 0 into registers (<= 3 float4 per thread)
    float4 pf[3];
#pragma unroll
    for (int k = 0; k < 3; k++) {
        int v = tid + k * 1024;
        if (v < CH_V4) pf[k] = x4[v];
    }

    float carry = 0.f;
    int buf = 0;

    for (int c = 0; c < NCHUNK; c++) {
        // Commit prefetched chunk c into smem buffer `buf`
        float4* s4 = (float4*)s_x[buf];
#pragma unroll
        for (int k = 0; k < 3; k++) {
            int v = tid + k * 1024;
            if (v < CH_V4) s4[v] = pf[k];
        }
        __syncthreads();

        // Kick off chunk c+1 loads (in flight during compute below)
        if (c + 1 < NCHUNK) {
            const float4* src = x4 + (size_t)(c + 1) * CH_V4;
#pragma unroll
            for (int k = 0; k < 3; k++) {
                int v = tid + k * 1024;
                if (v < CH_V4) pf[k] = src[v];
            }
        }

        // Row stats: thread tid handles row c*CHUNK + tid (tid < 1000)
        float v = 0.f;  // sdiff contribution; 0 for inactive lanes
        if (tid < CHUNK) {
            const float* xr = &s_x[buf][tid * D_DIM];  // stride 9: conflict-free
            float s1 = 0.f, s2 = 0.f, f1 = 0.f, f2 = 0.f;
#pragma unroll
            for (int d = 0; d < D_DIM; d++) {
                float xv = xr[d];
                float t1 = (xv - c1) * inv_a1;
                float t2 = (xv - c2) * inv_a2;
                s1 = fmaf(t1, t1, s1);
                s2 = fmaf(t2, t2, s2);
                f1 = fmaf(xv, w1r[d], f1);
                f2 = fmaf(xv, w2r[d], f2);
            }
            v = s2 - s1;
            const int r = c * CHUNK + tid;
            g_df[r] = f1 - f2;          // biases cancel in the difference? NO:
            g_f2[r] = f2 + b2v;         // keep both biases explicit below
            g_df[r] = (f1 + b1v) - (f2 + b2v);
        }

        // Block-wide inclusive scan of v over 1024 lanes (tid order)
        float ws = v;
#pragma unroll
        for (int off = 1; off < 32; off <<= 1) {
            float t = __shfl_up_sync(0xFFFFFFFFu, ws, off);
            if (lane >= off) ws += t;
        }
        if (lane == 31) s_warp[wid] = ws;
        __syncthreads();
        if (wid == 0) {
            float w = s_warp[lane];
#pragma unroll
            for (int off = 1; off < 32; off <<= 1) {
                float t = __shfl_up_sync(0xFFFFFFFFu, w, off);
                if (lane >= off) w += t;
            }
            s_warp[lane] = w;
        }
        __syncthreads();

        float incl = ws + ((wid > 0) ? s_warp[wid - 1] : 0.f);
        float block_total = s_warp[31];

        if (tid < CHUNK) {
            float Dv = carry + incl;
            g_wbar[c * CHUNK + tid] = 1.0f / (1.0f + expf(-Dv));
        }
        carry += block_total;

        __syncthreads();   // protect s_warp (and s_x[buf^1] reuse 2 iters out)
        buf ^= 1;
    }
}

// ---------------------------------------------------------------------------
// K3: out[i, j] = f2[i] + df[i] * wbar[j]
// Four rows per block: one wbar float4 load feeds four streaming stores.
// ---------------------------------------------------------------------------
__global__ void __launch_bounds__(256) k3_outer(float* __restrict__ out)
{
    const int r0 = blockIdx.x * 4;

    float f2v[4], dfv[4];
    float4* __restrict__ o[4];
#pragma unroll
    for (int k = 0; k < 4; k++) {
        f2v[k] = g_f2[r0 + k];
        dfv[k] = g_df[r0 + k];
        o[k]   = (float4*)(out + (size_t)(r0 + k) * N_ROWS);
    }

    const float4* __restrict__ wb4 = (const float4*)g_wbar;

#pragma unroll 2
    for (int j = threadIdx.x; j < N_ROWS / 4; j += 256) {
        float4 w = wb4[j];
#pragma unroll
        for (int k = 0; k < 4; k++) {
            float4 r;
            r.x = fmaf(dfv[k], w.x, f2v[k]);
            r.y = fmaf(dfv[k], w.y, f2v[k]);
            r.z = fmaf(dfv[k], w.z, f2v[k]);
            r.w = fmaf(dfv[k], w.w, f2v[k]);
            __stcs(&o[k][j], r);
        }
    }
}

// ---------------------------------------------------------------------------
extern "C" void kernel_launch(void* const* d_in, const int* in_sizes, int n_in,
                              void* d_out, int out_size)
{
    const float* x     = (const float*)d_in[0];
    const float* a1    = (const float*)d_in[1];
    const float* c1    = (const float*)d_in[2];
    const float* a2    = (const float*)d_in[3];
    const float* c2    = (const float*)d_in[4];
    const float* w_fc1 = (const float*)d_in[5];
    const float* b_fc1 = (const float*)d_in[6];
    const float* w_fc2 = (const float*)d_in[7];
    const float* b_fc2 = (const float*)d_in[8];
    float* out = (float*)d_out;

    k_prep<<<1, 1024>>>(x, a1, c1, a2, c2, w_fc1, b_fc1, w_fc2, b_fc2);
    k3_outer<<<N_ROWS / 4, 256>>>(out);
}

// round 9
// speedup vs baseline: 1.1275x; 1.1275x over previous
#include <cuda_runtime.h>
#include <math.h>

#define N_ROWS 8000
#define D_DIM  9
#define K1_ROWS 128   // rows per k1 block

// Scratch: device globals (no allocation allowed anywhere)
__device__ float g_sdiff[N_ROWS];  // s2 - s1
__device__ float g_df[N_ROWS];     // (f1+b1) - (f2+b2)
__device__ float g_f2[N_ROWS];     // f2 + b2
__device__ float g_wbar[N_ROWS];   // sigmoid(cumsum(sdiff))

// ---------------------------------------------------------------------------
// K1: per-row stats with smem staging for coalesced global loads.
// 128 threads handle 128 rows = 1152 floats = 288 float4 (contiguous).
// Per-row reads from smem, stride 9 (gcd(9,32)=1 -> conflict-free).
// ---------------------------------------------------------------------------
__global__ void __launch_bounds__(K1_ROWS) k1_rowstats(
    const float* __restrict__ x,
    const float* __restrict__ a1p, const float* __restrict__ c1p,
    const float* __restrict__ a2p, const float* __restrict__ c2p,
    const float* __restrict__ w1,  const float* __restrict__ b1,
    const float* __restrict__ w2,  const float* __restrict__ b2)
{
    __shared__ float s_x[K1_ROWS * D_DIM];

    const int row0   = blockIdx.x * K1_ROWS;
    const int n_rows = min(K1_ROWS, N_ROWS - row0);
    const int n_flt  = n_rows * D_DIM;

    const float4* __restrict__ x4 = (const float4*)(x + (size_t)row0 * D_DIM);
    float4* s4 = (float4*)s_x;
    const int n_vec = n_flt / 4;
    for (int v = threadIdx.x; v < n_vec; v += K1_ROWS) s4[v] = x4[v];
    for (int t = n_vec * 4 + threadIdx.x; t < n_flt; t += K1_ROWS)
        s_x[t] = x[(size_t)row0 * D_DIM + t];
    __syncthreads();

    const int r = threadIdx.x;
    if (r >= n_rows) return;
    const int i = row0 + r;

    const float a1 = a1p[0], c1 = c1p[0], a2 = a2p[0], c2 = c2p[0];
    const float inv_a1 = 1.0f / a1, inv_a2 = 1.0f / a2;

    float s1 = 0.f, s2 = 0.f, f1 = 0.f, f2 = 0.f;
#pragma unroll
    for (int d = 0; d < D_DIM; d++) {
        float xv = s_x[r * D_DIM + d];
        float t1 = (xv - c1) * inv_a1;
        float t2 = (xv - c2) * inv_a2;
        s1 = fmaf(t1, t1, s1);
        s2 = fmaf(t2, t2, s2);
        f1 = fmaf(xv, w1[d], f1);
        f2 = fmaf(xv, w2[d], f2);
    }
    g_sdiff[i] = s2 - s1;
    float f2b = f2 + b2[0];
    g_f2[i] = f2b;
    g_df[i] = (f1 + b1[0]) - f2b;
}

// ---------------------------------------------------------------------------
// K2: single-pass inclusive scan of 8000 elems -> wbar = sigmoid(prefix).
// 8000 = 1000 threads x 8 elems exactly; threads 1000..1023 contribute 0.
// Thread-serial scan -> warp shuffle scan -> smem hop for warp totals.
// ---------------------------------------------------------------------------
__global__ void __launch_bounds__(1024) k2_scan_sigmoid()
{
    __shared__ float s_warp[32];

    const int tid  = threadIdx.x;
    const int lane = tid & 31;
    const int wid  = tid >> 5;
    const bool active = (tid < 1000);

    float e[8] = {0.f, 0.f, 0.f, 0.f, 0.f, 0.f, 0.f, 0.f};
    if (active) {
        const float4* __restrict__ in4 = (const float4*)g_sdiff;
        float4 va = in4[2 * tid];       // indices 2*tid, 2*tid+1 < 2000: in range
        float4 vb = in4[2 * tid + 1];
        e[0] = va.x; e[1] = va.y; e[2] = va.z; e[3] = va.w;
        e[4] = vb.x; e[5] = vb.y; e[6] = vb.z; e[7] = vb.w;
    }
#pragma unroll
    for (int k = 1; k < 8; k++) e[k] += e[k - 1];
    float tot = e[7];

    float ws = tot;
#pragma unroll
    for (int off = 1; off < 32; off <<= 1) {
        float t = __shfl_up_sync(0xFFFFFFFFu, ws, off);
        if (lane >= off) ws += t;
    }
    if (lane == 31) s_warp[wid] = ws;
    __syncthreads();
    if (wid == 0) {
        float w = s_warp[lane];
#pragma unroll
        for (int off = 1; off < 32; off <<= 1) {
            float t = __shfl_up_sync(0xFFFFFFFFu, w, off);
            if (lane >= off) w += t;
        }
        s_warp[lane] = w;
    }
    __syncthreads();

    float warp_prefix   = (wid > 0) ? s_warp[wid - 1] : 0.f;
    float thread_prefix = warp_prefix + (ws - tot);  // exclusive over this thread

    if (active) {
        float o[8];
#pragma unroll
        for (int k = 0; k < 8; k++) {
            float Dv = thread_prefix + e[k];
            o[k] = 1.0f / (1.0f + expf(-Dv));
        }
        float4* __restrict__ out4 = (float4*)g_wbar;
        out4[2 * tid]     = make_float4(o[0], o[1], o[2], o[3]);
        out4[2 * tid + 1] = make_float4(o[4], o[5], o[6], o[7]);
    }
}

// ---------------------------------------------------------------------------
// K3: out[i, j] = f2[i] + df[i] * wbar[j]
// Two rows per block (proven best: regs=28, occ=79%), streaming stores.
// ---------------------------------------------------------------------------
__global__ void __launch_bounds__(256) k3_outer(float* __restrict__ out)
{
    const int rowA = blockIdx.x * 2;
    const int rowB = rowA + 1;

    const float f2A = g_f2[rowA];
    const float dfA = g_df[rowA];
    const float f2B = g_f2[rowB];
    const float dfB = g_df[rowB];

    const float4* __restrict__ wb4 = (const float4*)g_wbar;
    float4* __restrict__ oA = (float4*)(out + (size_t)rowA * N_ROWS);
    float4* __restrict__ oB = (float4*)(out + (size_t)rowB * N_ROWS);

#pragma unroll 4
    for (int j = threadIdx.x; j < N_ROWS / 4; j += 256) {
        float4 w = wb4[j];
        float4 rA, rB;
        rA.x = fmaf(dfA, w.x, f2A); rA.y = fmaf(dfA, w.y, f2A);
        rA.z = fmaf(dfA, w.z, f2A); rA.w = fmaf(dfA, w.w, f2A);
        rB.x = fmaf(dfB, w.x, f2B); rB.y = fmaf(dfB, w.y, f2B);
        rB.z = fmaf(dfB, w.z, f2B); rB.w = fmaf(dfB, w.w, f2B);
        __stcs(&oA[j], rA);
        __stcs(&oB[j], rB);
    }
}

// ---------------------------------------------------------------------------
extern "C" void kernel_launch(void* const* d_in, const int* in_sizes, int n_in,
                              void* d_out, int out_size)
{
    const float* x     = (const float*)d_in[0];
    const float* a1    = (const float*)d_in[1];
    const float* c1    = (const float*)d_in[2];
    const float* a2    = (const float*)d_in[3];
    const float* c2    = (const float*)d_in[4];
    const float* w_fc1 = (const float*)d_in[5];
    const float* b_fc1 = (const float*)d_in[6];
    const float* w_fc2 = (const float*)d_in[7];
    const float* b_fc2 = (const float*)d_in[8];
    float* out = (float*)d_out;

    k1_rowstats<<<(N_ROWS + K1_ROWS - 1) / K1_ROWS, K1_ROWS>>>(
        x, a1, c1, a2, c2, w_fc1, b_fc1, w_fc2, b_fc2);
    k2_scan_sigmoid<<<1, 1024>>>();
    k3_outer<<<N_ROWS / 2, 256>>>(out);
}